// round 14
// baseline (speedup 1.0000x reference)
#include <cuda_runtime.h>

#define TT   512
#define BB   2048
#define NTAG 16
#define LOG2E 1.4426950408889634f
#define LN2   0.6931471805599453f

typedef unsigned long long u64;

__device__ __forceinline__ float rcp_ap(float x)  { float r; asm("rcp.approx.f32 %0, %1;"  : "=f"(r) : "f"(x)); return r; }
__device__ __forceinline__ float ex2_ap(float x)  { float r; asm("ex2.approx.f32 %0, %1;"  : "=f"(r) : "f"(x)); return r; }
__device__ __forceinline__ float lg2_ap(float x)  { float r; asm("lg2.approx.f32 %0, %1;"  : "=f"(r) : "f"(x)); return r; }
__device__ __forceinline__ float cos_ap(float x)  { float r; asm("cos.approx.f32 %0, %1;"  : "=f"(r) : "f"(x)); return r; }
__device__ __forceinline__ float tanh_ap(float x) { float r; asm("tanh.approx.f32 %0, %1;" : "=f"(r) : "f"(x)); return r; }

// packed f32x2 helpers (sm_100+): one FFMA2 does 2 fp32 fmas (validated R5/R6)
__device__ __forceinline__ u64 pk(float lo, float hi) {
    u64 r; asm("mov.b64 %0, {%1, %2};" : "=l"(r) : "f"(lo), "f"(hi)); return r;
}
__device__ __forceinline__ void upk(u64 v, float& lo, float& hi) {
    asm("mov.b64 {%0, %1}, %2;" : "=f"(lo), "=f"(hi) : "l"(v));
}
__device__ __forceinline__ u64 fma2(u64 a, u64 b, u64 c) {
    u64 d; asm("fma.rn.f32x2 %0, %1, %2, %3;" : "=l"(d) : "l"(a), "l"(b), "l"(c)); return d;
}

// x-part of pre for one gate (4 wires), packed as two f32x2 accumulators.
__device__ __forceinline__ void xacc8(const float4& A, const float4& B,
    const u64* wxp01, const u64* wxp23, u64 th01, u64 th23, u64& o01, u64& o23)
{
    float xv[8] = {A.x, A.y, A.z, A.w, B.x, B.y, B.z, B.w};
    u64 p01 = th01, p23 = th23;
#pragma unroll
    for (int d = 0; d < 8; d++) {
        u64 xd = pk(xv[d], xv[d]);
        p01 = fma2(xd, wxp01[d], p01);
        p23 = fma2(xd, wxp23[d], p23);
    }
    o01 = p01; o23 = p23;
}

// ---------------------------------------------------------------------------
// Single fused kernel: LSTM recurrence + logits + log_softmax.
// R13 structure (best known, 154.2us) with three instruction-count cuts
// (kernel is measured issue-bound: issue=43.3% = 256/592 SMSPs at ~100%):
//  1. combine tanh(cx): Pade[7/6] (~10 instr) -> tanh.approx (1 MUFU).
//  2. xacc + pre Wh·h in packed f32x2 (FFMA2), numerics validated R5/R6.
//  3. unroll 4 -> 2 (loop body was ~32KB, past the L0/L1.5 I$).
// ---------------------------------------------------------------------------
__global__ void __launch_bounds__(32, 1)
fused_kernel(const float* __restrict__ x,
             const float* __restrict__ w_gates,
             const float* __restrict__ b_gates,
             const float* __restrict__ rx_theta,
             const float* __restrict__ w_tag,
             const float* __restrict__ b_tag,
             float* __restrict__ out)
{
    const int tid = blockIdx.x * 32 + threadIdx.x;   // 0..8191
    const int b   = tid >> 2;                        // batch chain 0..2047
    const int g   = tid & 3;                         // gate (f,i,g,o)

    // per-lane gate weights: w_gates layout (4,4,12): [g*48 + k*12 + d]
    float wx[4][8], wh[4][4], th[4];
#pragma unroll
    for (int k = 0; k < 4; k++) {
#pragma unroll
        for (int d = 0; d < 8; d++) wx[k][d] = w_gates[g*48 + k*12 + d];
#pragma unroll
        for (int j = 0; j < 4; j++) wh[k][j] = w_gates[g*48 + k*12 + 8 + j];
        th[k] = b_gates[g*4 + k] + rx_theta[g*4 + k];
    }
    // packed weight pairs (k=0,1) and (k=2,3)
    u64 wxp01[8], wxp23[8], whp01[4], whp23[4];
#pragma unroll
    for (int d = 0; d < 8; d++) { wxp01[d] = pk(wx[0][d], wx[1][d]); wxp23[d] = pk(wx[2][d], wx[3][d]); }
#pragma unroll
    for (int j = 0; j < 4; j++) { whp01[j] = pk(wh[0][j], wh[1][j]); whp23[j] = pk(wh[2][j], wh[3][j]); }
    u64 th01 = pk(th[0], th[1]), th23 = pk(th[2], th[3]);

    // lane 2 is the tanh gate; lanes 0,1,3 are sigmoid gates (exact ex2/rcp)
    const float gm = (g == 2) ?  2.0f * LOG2E : -LOG2E;
    const float gA = (g == 2) ? -2.0f         :  1.0f;
    const float gB = (g == 2) ?  1.0f         :  0.0f;

    // per-lane tag weights (tags 4g..4g+3), prescaled by LOG2E (log2 domain)
    float4 wt[4]; float bt[4];
#pragma unroll
    for (int k = 0; k < 4; k++) {
        float4 w = ((const float4*)w_tag)[g*4 + k];
        wt[k] = make_float4(w.x * LOG2E, w.y * LOG2E, w.z * LOG2E, w.w * LOG2E);
        bt[k] = b_tag[g*4 + k] * LOG2E;
    }

    float h0 = 0.f, h1 = 0.f, h2 = 0.f, h3 = 0.f;
    float cx[4] = {0.f, 0.f, 0.f, 0.f};

    const float4* xp = (const float4*)x;             // (t*BB + b)*2 indexing
    float4 xa[4], xb[4];                             // 4-deep prefetch ring
#pragma unroll
    for (int p = 0; p < 4; p++) {
        size_t i = ((size_t)p * BB + b) * 2;
        xa[p] = xp[i]; xb[p] = xp[i + 1];
    }

    // x-part of pre for t=0 (one step ahead, packed); consumes slot 0
    u64 xp01, xp23;
    xacc8(xa[0], xb[0], wxp01, wxp23, th01, th23, xp01, xp23);
    // slot 0 is next used at t=3 to build xacc(t=4) -> must hold x[4]
    {
        size_t i4 = ((size_t)4 * BB + b) * 2;
        xa[0] = xp[i4]; xb[0] = xp[i4 + 1];
    }

    float4* op = (float4*)out;                       // row stride 4 float4s

#pragma unroll 2
    for (int t = 0; t < TT; t++) {
        // ---- pre = xacc + Wh·h (packed) ; c = cos(pre) (h-critical path) ----
        u64 hb0 = pk(h0, h0), hb1 = pk(h1, h1), hb2 = pk(h2, h2), hb3 = pk(h3, h3);
        u64 p01 = fma2(hb0, whp01[0], xp01);
        p01 = fma2(hb1, whp01[1], p01);
        p01 = fma2(hb2, whp01[2], p01);
        p01 = fma2(hb3, whp01[3], p01);
        u64 p23 = fma2(hb0, whp23[0], xp23);
        p23 = fma2(hb1, whp23[1], p23);
        p23 = fma2(hb2, whp23[2], p23);
        p23 = fma2(hb3, whp23[3], p23);
        float pre0, pre1, pre2, pre3;
        upk(p01, pre0, pre1); upk(p23, pre2, pre3);
        float c0 = cos_ap(pre0), c1 = cos_ap(pre1), c2 = cos_ap(pre2), c3 = cos_ap(pre3);

        // ---- off-path: next step's packed x-part, then refill the ring ----
        {
            int slot = (t + 1) & 3;
            xacc8(xa[slot], xb[slot], wxp01, wxp23, th01, th23, xp01, xp23);
            int tp = t + 5; if (tp > TT - 1) tp = TT - 1;
            size_t i = ((size_t)tp * BB + b) * 2;
            xa[slot] = xp[i]; xb[slot] = xp[i + 1];
        }

        // ---- expvals: e0=c1c2c3, e1=c0c1, e2=e1c2, e3=e1t23 ----
        float t23 = c2 * c3;
        float e1  = c0 * c1;
        float e0  = c1 * t23;
        float e2  = e1 * c2;
        float e3  = e1 * t23;

        // ---- gate nonlinearity (exact): v = fma(A, rcp(ex2(m*e)+1), B) ----
        float v0 = fmaf(gA, rcp_ap(ex2_ap(gm * e0) + 1.0f), gB);
        float v1 = fmaf(gA, rcp_ap(ex2_ap(gm * e1) + 1.0f), gB);
        float v2 = fmaf(gA, rcp_ap(ex2_ap(gm * e2) + 1.0f), gB);
        float v3 = fmaf(gA, rcp_ap(ex2_ap(gm * e3) + 1.0f), gB);

        // ---- gather all 4 gate vectors into every lane (16 independent shfl) ----
        float tg0[4], tg1[4], tg2[4], tg3[4];
#pragma unroll
        for (int s = 0; s < 4; s++) {
            tg0[s] = __shfl_sync(0xffffffffu, v0, s, 4);
            tg1[s] = __shfl_sync(0xffffffffu, v1, s, 4);
            tg2[s] = __shfl_sync(0xffffffffu, v2, s, 4);
            tg3[s] = __shfl_sync(0xffffffffu, v3, s, 4);
        }
        // tgK[s] = gate-s value for wire K. s: 0=f, 1=i, 2=g, 3=o.

        // ---- combine (replicated); tanh(cx) via MUFU.TANH (1 instr) ----
        float hn[4];
#pragma unroll
        for (int k = 0; k < 4; k++) {
            float F = (k==0)?tg0[0]:(k==1)?tg1[0]:(k==2)?tg2[0]:tg3[0];
            float I = (k==0)?tg0[1]:(k==1)?tg1[1]:(k==2)?tg2[1]:tg3[1];
            float G = (k==0)?tg0[2]:(k==1)?tg1[2]:(k==2)?tg2[2]:tg3[2];
            float O = (k==0)?tg0[3]:(k==1)?tg1[3]:(k==2)?tg2[3]:tg3[3];
            float nc = fmaf(F, cx[k], I * G);
            cx[k] = nc;
            hn[k] = O * tanh_ap(nc);                     // o * tanh(cx)
        }
        h0 = hn[0]; h1 = hn[1]; h2 = hn[2]; h3 = hn[3];

        // ---- fused output epilogue (log2-domain logits, quad softmax) ----
        float l0 = fmaf(h3, wt[0].w, fmaf(h2, wt[0].z, fmaf(h1, wt[0].y, fmaf(h0, wt[0].x, bt[0]))));
        float l1 = fmaf(h3, wt[1].w, fmaf(h2, wt[1].z, fmaf(h1, wt[1].y, fmaf(h0, wt[1].x, bt[1]))));
        float l2 = fmaf(h3, wt[2].w, fmaf(h2, wt[2].z, fmaf(h1, wt[2].y, fmaf(h0, wt[2].x, bt[2]))));
        float l3 = fmaf(h3, wt[3].w, fmaf(h2, wt[3].z, fmaf(h1, wt[3].y, fmaf(h0, wt[3].x, bt[3]))));
        float s4 = (ex2_ap(l0) + ex2_ap(l1)) + (ex2_ap(l2) + ex2_ap(l3));
        s4 += __shfl_xor_sync(0xffffffffu, s4, 1);
        s4 += __shfl_xor_sync(0xffffffffu, s4, 2);
        float lsl = lg2_ap(s4);
        float4 o = make_float4((l0 - lsl) * LN2, (l1 - lsl) * LN2,
                               (l2 - lsl) * LN2, (l3 - lsl) * LN2);
        op[((size_t)t * BB + b) * 4 + g] = o;
    }
}

extern "C" void kernel_launch(void* const* d_in, const int* in_sizes, int n_in,
                              void* d_out, int out_size)
{
    const float* x        = (const float*)d_in[0];
    const float* w_gates  = (const float*)d_in[1];
    const float* b_gates  = (const float*)d_in[2];
    const float* rx_theta = (const float*)d_in[3];
    const float* w_tag    = (const float*)d_in[4];
    const float* b_tag    = (const float*)d_in[5];

    fused_kernel<<<256, 32>>>(x, w_gates, b_gates, rx_theta,
                              w_tag, b_tag, (float*)d_out);
}

// round 15
// speedup vs baseline: 1.5459x; 1.5459x over previous
#include <cuda_runtime.h>

#define TT   512
#define BB   2048
#define NTAG 16
#define LOG2E 1.4426950408889634f
#define LN2   0.6931471805599453f

__device__ __forceinline__ float rcp_ap(float x)  { float r; asm("rcp.approx.f32 %0, %1;"  : "=f"(r) : "f"(x)); return r; }
__device__ __forceinline__ float ex2_ap(float x)  { float r; asm("ex2.approx.f32 %0, %1;"  : "=f"(r) : "f"(x)); return r; }
__device__ __forceinline__ float lg2_ap(float x)  { float r; asm("lg2.approx.f32 %0, %1;"  : "=f"(r) : "f"(x)); return r; }
__device__ __forceinline__ float cos_ap(float x)  { float r; asm("cos.approx.f32 %0, %1;"  : "=f"(r) : "f"(x)); return r; }
__device__ __forceinline__ float tanh_ap(float x) { float r; asm("tanh.approx.f32 %0, %1;" : "=f"(r) : "f"(x)); return r; }

// ---------------------------------------------------------------------------
// Single fused kernel: LSTM recurrence + logits + log_softmax.
// Byte-identical to R13 (best known, 154.2us) EXCEPT ONE CHANGE:
// combine tanh(cx) uses MUFU.TANH (1 instr) instead of Pade[7/6] (~10 instr
// x 4 wires = -36 instr/step). Numerics of this exact substitution measured
// in R14: rel_err 1.6e-7 (gates stay exact; recurrence contracts, f<=0.73).
// Kernel is measured issue-bound (R13: issue=43.3% = 256warps/592SMSP at
// ~100% per-warp issue), so -7% instructions => -7% time.
// ---------------------------------------------------------------------------
__global__ void __launch_bounds__(32, 1)
fused_kernel(const float* __restrict__ x,
             const float* __restrict__ w_gates,
             const float* __restrict__ b_gates,
             const float* __restrict__ rx_theta,
             const float* __restrict__ w_tag,
             const float* __restrict__ b_tag,
             float* __restrict__ out)
{
    const int tid = blockIdx.x * 32 + threadIdx.x;   // 0..8191
    const int b   = tid >> 2;                        // batch chain 0..2047
    const int g   = tid & 3;                         // gate (f,i,g,o)

    // per-lane gate weights: w_gates layout (4,4,12): [g*48 + k*12 + d]
    float wx[4][8], wh[4][4], th[4];
#pragma unroll
    for (int k = 0; k < 4; k++) {
#pragma unroll
        for (int d = 0; d < 8; d++) wx[k][d] = w_gates[g*48 + k*12 + d];
#pragma unroll
        for (int j = 0; j < 4; j++) wh[k][j] = w_gates[g*48 + k*12 + 8 + j];
        th[k] = b_gates[g*4 + k] + rx_theta[g*4 + k];
    }
    // lane 2 is the tanh gate; lanes 0,1,3 are sigmoid gates
    const float gm = (g == 2) ?  2.0f * LOG2E : -LOG2E;
    const float gA = (g == 2) ? -2.0f         :  1.0f;
    const float gB = (g == 2) ?  1.0f         :  0.0f;

    // per-lane tag weights (tags 4g..4g+3), prescaled by LOG2E (log2 domain)
    float4 wt[4]; float bt[4];
#pragma unroll
    for (int k = 0; k < 4; k++) {
        float4 w = ((const float4*)w_tag)[g*4 + k];
        wt[k] = make_float4(w.x * LOG2E, w.y * LOG2E, w.z * LOG2E, w.w * LOG2E);
        bt[k] = b_tag[g*4 + k] * LOG2E;
    }

    float h0 = 0.f, h1 = 0.f, h2 = 0.f, h3 = 0.f;
    float cx[4] = {0.f, 0.f, 0.f, 0.f};

    const float4* xp = (const float4*)x;             // (t*BB + b)*2 indexing
    float4 xa[4], xb[4];                             // 4-deep prefetch ring
#pragma unroll
    for (int p = 0; p < 4; p++) {
        size_t i = ((size_t)p * BB + b) * 2;
        xa[p] = xp[i]; xb[p] = xp[i + 1];
    }

    // x-part of pre for t=0 (one step ahead); consumes slot 0
    float xacc[4];
    {
        float xv[8] = {xa[0].x, xa[0].y, xa[0].z, xa[0].w,
                       xb[0].x, xb[0].y, xb[0].z, xb[0].w};
#pragma unroll
        for (int k = 0; k < 4; k++) {
            float q = fmaf(xv[0], wx[k][0], th[k]);
            q = fmaf(xv[1], wx[k][1], q); q = fmaf(xv[2], wx[k][2], q);
            q = fmaf(xv[3], wx[k][3], q); q = fmaf(xv[4], wx[k][4], q);
            q = fmaf(xv[5], wx[k][5], q); q = fmaf(xv[6], wx[k][6], q);
            xacc[k] = fmaf(xv[7], wx[k][7], q);
        }
    }
    // slot 0 is next used at t=3 to build xacc(t=4) -> must hold x[4]
    {
        size_t i4 = ((size_t)4 * BB + b) * 2;
        xa[0] = xp[i4]; xb[0] = xp[i4 + 1];
    }

    float4* op = (float4*)out;                       // row stride 4 float4s

#pragma unroll 4
    for (int t = 0; t < TT; t++) {
        // ---- pre = xacc + Wh·h ; c = cos(pre) (h-critical path) ----
        float c0, c1, c2, c3;
        {
            float s0, s1;
            s0 = fmaf(h1, wh[0][1], fmaf(h0, wh[0][0], xacc[0]));
            s1 = fmaf(h3, wh[0][3], h2 * wh[0][2]);
            c0 = cos_ap(s0 + s1);
            s0 = fmaf(h1, wh[1][1], fmaf(h0, wh[1][0], xacc[1]));
            s1 = fmaf(h3, wh[1][3], h2 * wh[1][2]);
            c1 = cos_ap(s0 + s1);
            s0 = fmaf(h1, wh[2][1], fmaf(h0, wh[2][0], xacc[2]));
            s1 = fmaf(h3, wh[2][3], h2 * wh[2][2]);
            c2 = cos_ap(s0 + s1);
            s0 = fmaf(h1, wh[3][1], fmaf(h0, wh[3][0], xacc[3]));
            s1 = fmaf(h3, wh[3][3], h2 * wh[3][2]);
            c3 = cos_ap(s0 + s1);
        }

        // ---- off-path: compute next step's x-part, then refill the ring ----
        {
            int slot = (t + 1) & 3;
            float xv[8] = {xa[slot].x, xa[slot].y, xa[slot].z, xa[slot].w,
                           xb[slot].x, xb[slot].y, xb[slot].z, xb[slot].w};
#pragma unroll
            for (int k = 0; k < 4; k++) {
                float q = fmaf(xv[0], wx[k][0], th[k]);
                q = fmaf(xv[1], wx[k][1], q); q = fmaf(xv[2], wx[k][2], q);
                q = fmaf(xv[3], wx[k][3], q); q = fmaf(xv[4], wx[k][4], q);
                q = fmaf(xv[5], wx[k][5], q); q = fmaf(xv[6], wx[k][6], q);
                xacc[k] = fmaf(xv[7], wx[k][7], q);
            }
            int tp = t + 5; if (tp > TT - 1) tp = TT - 1;
            size_t i = ((size_t)tp * BB + b) * 2;
            xa[slot] = xp[i]; xb[slot] = xp[i + 1];
        }

        // ---- expvals: e0=c1c2c3, e1=c0c1, e2=e1c2, e3=e1t23 ----
        float t23 = c2 * c3;
        float e1  = c0 * c1;
        float e0  = c1 * t23;
        float e2  = e1 * c2;
        float e3  = e1 * t23;

        // ---- gate nonlinearity (exact): v = fma(A, rcp(ex2(m*e)+1), B) ----
        float v0 = fmaf(gA, rcp_ap(ex2_ap(gm * e0) + 1.0f), gB);
        float v1 = fmaf(gA, rcp_ap(ex2_ap(gm * e1) + 1.0f), gB);
        float v2 = fmaf(gA, rcp_ap(ex2_ap(gm * e2) + 1.0f), gB);
        float v3 = fmaf(gA, rcp_ap(ex2_ap(gm * e3) + 1.0f), gB);

        // ---- gather all 4 gate vectors into every lane (16 independent shfl) ----
        float tg0[4], tg1[4], tg2[4], tg3[4];
#pragma unroll
        for (int s = 0; s < 4; s++) {
            tg0[s] = __shfl_sync(0xffffffffu, v0, s, 4);
            tg1[s] = __shfl_sync(0xffffffffu, v1, s, 4);
            tg2[s] = __shfl_sync(0xffffffffu, v2, s, 4);
            tg3[s] = __shfl_sync(0xffffffffu, v3, s, 4);
        }
        // tgK[s] = gate-s value for wire K. s: 0=f, 1=i, 2=g, 3=o.

        // ---- combine (replicated); tanh(cx) via MUFU.TANH (1 instr) ----
        float hn[4];
#pragma unroll
        for (int k = 0; k < 4; k++) {
            float F = (k==0)?tg0[0]:(k==1)?tg1[0]:(k==2)?tg2[0]:tg3[0];
            float I = (k==0)?tg0[1]:(k==1)?tg1[1]:(k==2)?tg2[1]:tg3[1];
            float G = (k==0)?tg0[2]:(k==1)?tg1[2]:(k==2)?tg2[2]:tg3[2];
            float O = (k==0)?tg0[3]:(k==1)?tg1[3]:(k==2)?tg2[3]:tg3[3];
            float nc = fmaf(F, cx[k], I * G);
            cx[k] = nc;
            hn[k] = O * tanh_ap(nc);                     // o * tanh(cx)
        }
        h0 = hn[0]; h1 = hn[1]; h2 = hn[2]; h3 = hn[3];

        // ---- fused output epilogue (log2-domain logits, quad softmax) ----
        float l0 = fmaf(h3, wt[0].w, fmaf(h2, wt[0].z, fmaf(h1, wt[0].y, fmaf(h0, wt[0].x, bt[0]))));
        float l1 = fmaf(h3, wt[1].w, fmaf(h2, wt[1].z, fmaf(h1, wt[1].y, fmaf(h0, wt[1].x, bt[1]))));
        float l2 = fmaf(h3, wt[2].w, fmaf(h2, wt[2].z, fmaf(h1, wt[2].y, fmaf(h0, wt[2].x, bt[2]))));
        float l3 = fmaf(h3, wt[3].w, fmaf(h2, wt[3].z, fmaf(h1, wt[3].y, fmaf(h0, wt[3].x, bt[3]))));
        float s4 = (ex2_ap(l0) + ex2_ap(l1)) + (ex2_ap(l2) + ex2_ap(l3));
        s4 += __shfl_xor_sync(0xffffffffu, s4, 1);
        s4 += __shfl_xor_sync(0xffffffffu, s4, 2);
        float lsl = lg2_ap(s4);
        float4 o = make_float4((l0 - lsl) * LN2, (l1 - lsl) * LN2,
                               (l2 - lsl) * LN2, (l3 - lsl) * LN2);
        op[((size_t)t * BB + b) * 4 + g] = o;
    }
}

extern "C" void kernel_launch(void* const* d_in, const int* in_sizes, int n_in,
                              void* d_out, int out_size)
{
    const float* x        = (const float*)d_in[0];
    const float* w_gates  = (const float*)d_in[1];
    const float* b_gates  = (const float*)d_in[2];
    const float* rx_theta = (const float*)d_in[3];
    const float* w_tag    = (const float*)d_in[4];
    const float* b_tag    = (const float*)d_in[5];

    fused_kernel<<<256, 32>>>(x, w_gates, b_gates, rx_theta,
                              w_tag, b_tag, (float*)d_out);
}

// round 16
// speedup vs baseline: 1.8020x; 1.1657x over previous
#include <cuda_runtime.h>

#define TT   512
#define BB   2048
#define NTAG 16
#define LOG2E 1.4426950408889634f
#define LN2   0.6931471805599453f

__device__ __forceinline__ float rcp_ap(float x)  { float r; asm("rcp.approx.f32 %0, %1;"  : "=f"(r) : "f"(x)); return r; }
__device__ __forceinline__ float ex2_ap(float x)  { float r; asm("ex2.approx.f32 %0, %1;"  : "=f"(r) : "f"(x)); return r; }
__device__ __forceinline__ float lg2_ap(float x)  { float r; asm("lg2.approx.f32 %0, %1;"  : "=f"(r) : "f"(x)); return r; }
__device__ __forceinline__ float cos_ap(float x)  { float r; asm("cos.approx.f32 %0, %1;"  : "=f"(r) : "f"(x)); return r; }
__device__ __forceinline__ float tanh_ap(float x) { float r; asm("tanh.approx.f32 %0, %1;" : "=f"(r) : "f"(x)); return r; }

// ---------------------------------------------------------------------------
// Single fused kernel: LSTM recurrence + logits + log_softmax.
// Byte-identical to R15 (best known, 142.1us) EXCEPT ONE CHANGE:
// gate nonlinearity via MUFU.TANH identity instead of ex2/rcp chain:
//   sigmoid(e) = 0.5 + 0.5*tanh(e/2)  (0.5 prescale folded into c1)
//   tanh gate  = tanh(e)
// 4 x (mul+ex2+add+rcp+fma)=20 instr -> 1 mul + 4 x (tanh+fma)=9 instr.
// tanh.approx error class measured in R14/R15 at ~1e-7 total; gate inputs
// are bounded |u|<=1 (products of cosines) where MUFU.TANH is most accurate.
// ---------------------------------------------------------------------------
__global__ void __launch_bounds__(32, 1)
fused_kernel(const float* __restrict__ x,
             const float* __restrict__ w_gates,
             const float* __restrict__ b_gates,
             const float* __restrict__ rx_theta,
             const float* __restrict__ w_tag,
             const float* __restrict__ b_tag,
             float* __restrict__ out)
{
    const int tid = blockIdx.x * 32 + threadIdx.x;   // 0..8191
    const int b   = tid >> 2;                        // batch chain 0..2047
    const int g   = tid & 3;                         // gate (f,i,g,o)

    // per-lane gate weights: w_gates layout (4,4,12): [g*48 + k*12 + d]
    float wx[4][8], wh[4][4], th[4];
#pragma unroll
    for (int k = 0; k < 4; k++) {
#pragma unroll
        for (int d = 0; d < 8; d++) wx[k][d] = w_gates[g*48 + k*12 + d];
#pragma unroll
        for (int j = 0; j < 4; j++) wh[k][j] = w_gates[g*48 + k*12 + 8 + j];
        th[k] = b_gates[g*4 + k] + rx_theta[g*4 + k];
    }
    // lane 2 = tanh gate; lanes 0,1,3 = sigmoid: sig(e) = 0.5 + 0.5*tanh(e/2)
    const float gm = (g == 2) ? 1.0f : 0.5f;   // folded into c1
    const float gA = (g == 2) ? 1.0f : 0.5f;
    const float gB = (g == 2) ? 0.0f : 0.5f;

    // per-lane tag weights (tags 4g..4g+3), prescaled by LOG2E (log2 domain)
    float4 wt[4]; float bt[4];
#pragma unroll
    for (int k = 0; k < 4; k++) {
        float4 w = ((const float4*)w_tag)[g*4 + k];
        wt[k] = make_float4(w.x * LOG2E, w.y * LOG2E, w.z * LOG2E, w.w * LOG2E);
        bt[k] = b_tag[g*4 + k] * LOG2E;
    }

    float h0 = 0.f, h1 = 0.f, h2 = 0.f, h3 = 0.f;
    float cx[4] = {0.f, 0.f, 0.f, 0.f};

    const float4* xp = (const float4*)x;             // (t*BB + b)*2 indexing
    float4 xa[4], xb[4];                             // 4-deep prefetch ring
#pragma unroll
    for (int p = 0; p < 4; p++) {
        size_t i = ((size_t)p * BB + b) * 2;
        xa[p] = xp[i]; xb[p] = xp[i + 1];
    }

    // x-part of pre for t=0 (one step ahead); consumes slot 0
    float xacc[4];
    {
        float xv[8] = {xa[0].x, xa[0].y, xa[0].z, xa[0].w,
                       xb[0].x, xb[0].y, xb[0].z, xb[0].w};
#pragma unroll
        for (int k = 0; k < 4; k++) {
            float q = fmaf(xv[0], wx[k][0], th[k]);
            q = fmaf(xv[1], wx[k][1], q); q = fmaf(xv[2], wx[k][2], q);
            q = fmaf(xv[3], wx[k][3], q); q = fmaf(xv[4], wx[k][4], q);
            q = fmaf(xv[5], wx[k][5], q); q = fmaf(xv[6], wx[k][6], q);
            xacc[k] = fmaf(xv[7], wx[k][7], q);
        }
    }
    // slot 0 is next used at t=3 to build xacc(t=4) -> must hold x[4]
    {
        size_t i4 = ((size_t)4 * BB + b) * 2;
        xa[0] = xp[i4]; xb[0] = xp[i4 + 1];
    }

    float4* op = (float4*)out;                       // row stride 4 float4s

#pragma unroll 4
    for (int t = 0; t < TT; t++) {
        // ---- pre = xacc + Wh·h ; c = cos(pre) (h-critical path) ----
        float c0, c1, c2, c3;
        {
            float s0, s1;
            s0 = fmaf(h1, wh[0][1], fmaf(h0, wh[0][0], xacc[0]));
            s1 = fmaf(h3, wh[0][3], h2 * wh[0][2]);
            c0 = cos_ap(s0 + s1);
            s0 = fmaf(h1, wh[1][1], fmaf(h0, wh[1][0], xacc[1]));
            s1 = fmaf(h3, wh[1][3], h2 * wh[1][2]);
            c1 = cos_ap(s0 + s1);
            s0 = fmaf(h1, wh[2][1], fmaf(h0, wh[2][0], xacc[2]));
            s1 = fmaf(h3, wh[2][3], h2 * wh[2][2]);
            c2 = cos_ap(s0 + s1);
            s0 = fmaf(h1, wh[3][1], fmaf(h0, wh[3][0], xacc[3]));
            s1 = fmaf(h3, wh[3][3], h2 * wh[3][2]);
            c3 = cos_ap(s0 + s1);
        }

        // ---- off-path: compute next step's x-part, then refill the ring ----
        {
            int slot = (t + 1) & 3;
            float xv[8] = {xa[slot].x, xa[slot].y, xa[slot].z, xa[slot].w,
                           xb[slot].x, xb[slot].y, xb[slot].z, xb[slot].w};
#pragma unroll
            for (int k = 0; k < 4; k++) {
                float q = fmaf(xv[0], wx[k][0], th[k]);
                q = fmaf(xv[1], wx[k][1], q); q = fmaf(xv[2], wx[k][2], q);
                q = fmaf(xv[3], wx[k][3], q); q = fmaf(xv[4], wx[k][4], q);
                q = fmaf(xv[5], wx[k][5], q); q = fmaf(xv[6], wx[k][6], q);
                xacc[k] = fmaf(xv[7], wx[k][7], q);
            }
            int tp = t + 5; if (tp > TT - 1) tp = TT - 1;
            size_t i = ((size_t)tp * BB + b) * 2;
            xa[slot] = xp[i]; xb[slot] = xp[i + 1];
        }

        // ---- expvals (gm folded into c1): u_k = gate input ----
        float c1s = gm * c1;
        float t23 = c2 * c3;
        float u1  = c0 * c1s;
        float u0  = c1s * t23;
        float u2  = u1 * c2;
        float u3  = u1 * t23;

        // ---- gate nonlinearity: v = fma(A, tanh(u), B)  (1 MUFU each) ----
        float v0 = fmaf(gA, tanh_ap(u0), gB);
        float v1 = fmaf(gA, tanh_ap(u1), gB);
        float v2 = fmaf(gA, tanh_ap(u2), gB);
        float v3 = fmaf(gA, tanh_ap(u3), gB);

        // ---- gather all 4 gate vectors into every lane (16 independent shfl) ----
        float tg0[4], tg1[4], tg2[4], tg3[4];
#pragma unroll
        for (int s = 0; s < 4; s++) {
            tg0[s] = __shfl_sync(0xffffffffu, v0, s, 4);
            tg1[s] = __shfl_sync(0xffffffffu, v1, s, 4);
            tg2[s] = __shfl_sync(0xffffffffu, v2, s, 4);
            tg3[s] = __shfl_sync(0xffffffffu, v3, s, 4);
        }
        // tgK[s] = gate-s value for wire K. s: 0=f, 1=i, 2=g, 3=o.

        // ---- combine (replicated); tanh(cx) via MUFU.TANH (1 instr) ----
        float hn[4];
#pragma unroll
        for (int k = 0; k < 4; k++) {
            float F = (k==0)?tg0[0]:(k==1)?tg1[0]:(k==2)?tg2[0]:tg3[0];
            float I = (k==0)?tg0[1]:(k==1)?tg1[1]:(k==2)?tg2[1]:tg3[1];
            float G = (k==0)?tg0[2]:(k==1)?tg1[2]:(k==2)?tg2[2]:tg3[2];
            float O = (k==0)?tg0[3]:(k==1)?tg1[3]:(k==2)?tg2[3]:tg3[3];
            float nc = fmaf(F, cx[k], I * G);
            cx[k] = nc;
            hn[k] = O * tanh_ap(nc);                     // o * tanh(cx)
        }
        h0 = hn[0]; h1 = hn[1]; h2 = hn[2]; h3 = hn[3];

        // ---- fused output epilogue (log2-domain logits, quad softmax) ----
        float l0 = fmaf(h3, wt[0].w, fmaf(h2, wt[0].z, fmaf(h1, wt[0].y, fmaf(h0, wt[0].x, bt[0]))));
        float l1 = fmaf(h3, wt[1].w, fmaf(h2, wt[1].z, fmaf(h1, wt[1].y, fmaf(h0, wt[1].x, bt[1]))));
        float l2 = fmaf(h3, wt[2].w, fmaf(h2, wt[2].z, fmaf(h1, wt[2].y, fmaf(h0, wt[2].x, bt[2]))));
        float l3 = fmaf(h3, wt[3].w, fmaf(h2, wt[3].z, fmaf(h1, wt[3].y, fmaf(h0, wt[3].x, bt[3]))));
        float s4 = (ex2_ap(l0) + ex2_ap(l1)) + (ex2_ap(l2) + ex2_ap(l3));
        s4 += __shfl_xor_sync(0xffffffffu, s4, 1);
        s4 += __shfl_xor_sync(0xffffffffu, s4, 2);
        float lsl = lg2_ap(s4);
        float4 o = make_float4((l0 - lsl) * LN2, (l1 - lsl) * LN2,
                               (l2 - lsl) * LN2, (l3 - lsl) * LN2);
        op[((size_t)t * BB + b) * 4 + g] = o;
    }
}

extern "C" void kernel_launch(void* const* d_in, const int* in_sizes, int n_in,
                              void* d_out, int out_size)
{
    const float* x        = (const float*)d_in[0];
    const float* w_gates  = (const float*)d_in[1];
    const float* b_gates  = (const float*)d_in[2];
    const float* rx_theta = (const float*)d_in[3];
    const float* w_tag    = (const float*)d_in[4];
    const float* b_tag    = (const float*)d_in[5];

    fused_kernel<<<256, 32>>>(x, w_gates, b_gates, rx_theta,
                              w_tag, b_tag, (float*)d_out);
}

// round 17
// speedup vs baseline: 1.8030x; 1.0005x over previous
#include <cuda_runtime.h>

#define TT   512
#define BB   2048
#define NTAG 16
#define LOG2E 1.4426950408889634f
#define LN2   0.6931471805599453f

__device__ __forceinline__ float rcp_ap(float x)  { float r; asm("rcp.approx.f32 %0, %1;"  : "=f"(r) : "f"(x)); return r; }
__device__ __forceinline__ float ex2_ap(float x)  { float r; asm("ex2.approx.f32 %0, %1;"  : "=f"(r) : "f"(x)); return r; }
__device__ __forceinline__ float lg2_ap(float x)  { float r; asm("lg2.approx.f32 %0, %1;"  : "=f"(r) : "f"(x)); return r; }
__device__ __forceinline__ float cos_ap(float x)  { float r; asm("cos.approx.f32 %0, %1;"  : "=f"(r) : "f"(x)); return r; }
__device__ __forceinline__ float tanh_ap(float x) { float r; asm("tanh.approx.f32 %0, %1;" : "=f"(r) : "f"(x)); return r; }

// ---------------------------------------------------------------------------
// Single fused kernel: LSTM recurrence + logits + log_softmax.
// Byte-identical to R16 (best known, 121.9us) EXCEPT ONE CHANGE:
// 64-thread blocks x 128 blocks (was 32 x 256). With 32-thread blocks, the
// 108 SMs holding 2 blocks put BOTH warps on SMSP 0 (warp-slot = wid%4, and
// every block's only warp has wid=0) -> 2x issue load on one scheduler.
// 64-thread blocks place the two warps on SMSP 0 and 1 -> 1 warp/SMSP.
// Kernel is measured issue-slot-bound (R16: ~150 instr/step, wall matches
// 2x150x512 cyc on doubly-loaded SMSPs; chain is only ~57K cyc).
// ---------------------------------------------------------------------------
__global__ void __launch_bounds__(64, 1)
fused_kernel(const float* __restrict__ x,
             const float* __restrict__ w_gates,
             const float* __restrict__ b_gates,
             const float* __restrict__ rx_theta,
             const float* __restrict__ w_tag,
             const float* __restrict__ b_tag,
             float* __restrict__ out)
{
    const int tid = blockIdx.x * 64 + threadIdx.x;   // 0..8191
    const int b   = tid >> 2;                        // batch chain 0..2047
    const int g   = tid & 3;                         // gate (f,i,g,o)

    // per-lane gate weights: w_gates layout (4,4,12): [g*48 + k*12 + d]
    float wx[4][8], wh[4][4], th[4];
#pragma unroll
    for (int k = 0; k < 4; k++) {
#pragma unroll
        for (int d = 0; d < 8; d++) wx[k][d] = w_gates[g*48 + k*12 + d];
#pragma unroll
        for (int j = 0; j < 4; j++) wh[k][j] = w_gates[g*48 + k*12 + 8 + j];
        th[k] = b_gates[g*4 + k] + rx_theta[g*4 + k];
    }
    // lane 2 = tanh gate; lanes 0,1,3 = sigmoid: sig(e) = 0.5 + 0.5*tanh(e/2)
    const float gm = (g == 2) ? 1.0f : 0.5f;   // folded into c1
    const float gA = (g == 2) ? 1.0f : 0.5f;
    const float gB = (g == 2) ? 0.0f : 0.5f;

    // per-lane tag weights (tags 4g..4g+3), prescaled by LOG2E (log2 domain)
    float4 wt[4]; float bt[4];
#pragma unroll
    for (int k = 0; k < 4; k++) {
        float4 w = ((const float4*)w_tag)[g*4 + k];
        wt[k] = make_float4(w.x * LOG2E, w.y * LOG2E, w.z * LOG2E, w.w * LOG2E);
        bt[k] = b_tag[g*4 + k] * LOG2E;
    }

    float h0 = 0.f, h1 = 0.f, h2 = 0.f, h3 = 0.f;
    float cx[4] = {0.f, 0.f, 0.f, 0.f};

    const float4* xp = (const float4*)x;             // (t*BB + b)*2 indexing
    float4 xa[4], xb[4];                             // 4-deep prefetch ring
#pragma unroll
    for (int p = 0; p < 4; p++) {
        size_t i = ((size_t)p * BB + b) * 2;
        xa[p] = xp[i]; xb[p] = xp[i + 1];
    }

    // x-part of pre for t=0 (one step ahead); consumes slot 0
    float xacc[4];
    {
        float xv[8] = {xa[0].x, xa[0].y, xa[0].z, xa[0].w,
                       xb[0].x, xb[0].y, xb[0].z, xb[0].w};
#pragma unroll
        for (int k = 0; k < 4; k++) {
            float q = fmaf(xv[0], wx[k][0], th[k]);
            q = fmaf(xv[1], wx[k][1], q); q = fmaf(xv[2], wx[k][2], q);
            q = fmaf(xv[3], wx[k][3], q); q = fmaf(xv[4], wx[k][4], q);
            q = fmaf(xv[5], wx[k][5], q); q = fmaf(xv[6], wx[k][6], q);
            xacc[k] = fmaf(xv[7], wx[k][7], q);
        }
    }
    // slot 0 is next used at t=3 to build xacc(t=4) -> must hold x[4]
    {
        size_t i4 = ((size_t)4 * BB + b) * 2;
        xa[0] = xp[i4]; xb[0] = xp[i4 + 1];
    }

    float4* op = (float4*)out;                       // row stride 4 float4s

#pragma unroll 4
    for (int t = 0; t < TT; t++) {
        // ---- pre = xacc + Wh·h ; c = cos(pre) (h-critical path) ----
        float c0, c1, c2, c3;
        {
            float s0, s1;
            s0 = fmaf(h1, wh[0][1], fmaf(h0, wh[0][0], xacc[0]));
            s1 = fmaf(h3, wh[0][3], h2 * wh[0][2]);
            c0 = cos_ap(s0 + s1);
            s0 = fmaf(h1, wh[1][1], fmaf(h0, wh[1][0], xacc[1]));
            s1 = fmaf(h3, wh[1][3], h2 * wh[1][2]);
            c1 = cos_ap(s0 + s1);
            s0 = fmaf(h1, wh[2][1], fmaf(h0, wh[2][0], xacc[2]));
            s1 = fmaf(h3, wh[2][3], h2 * wh[2][2]);
            c2 = cos_ap(s0 + s1);
            s0 = fmaf(h1, wh[3][1], fmaf(h0, wh[3][0], xacc[3]));
            s1 = fmaf(h3, wh[3][3], h2 * wh[3][2]);
            c3 = cos_ap(s0 + s1);
        }

        // ---- off-path: compute next step's x-part, then refill the ring ----
        {
            int slot = (t + 1) & 3;
            float xv[8] = {xa[slot].x, xa[slot].y, xa[slot].z, xa[slot].w,
                           xb[slot].x, xb[slot].y, xb[slot].z, xb[slot].w};
#pragma unroll
            for (int k = 0; k < 4; k++) {
                float q = fmaf(xv[0], wx[k][0], th[k]);
                q = fmaf(xv[1], wx[k][1], q); q = fmaf(xv[2], wx[k][2], q);
                q = fmaf(xv[3], wx[k][3], q); q = fmaf(xv[4], wx[k][4], q);
                q = fmaf(xv[5], wx[k][5], q); q = fmaf(xv[6], wx[k][6], q);
                xacc[k] = fmaf(xv[7], wx[k][7], q);
            }
            int tp = t + 5; if (tp > TT - 1) tp = TT - 1;
            size_t i = ((size_t)tp * BB + b) * 2;
            xa[slot] = xp[i]; xb[slot] = xp[i + 1];
        }

        // ---- expvals (gm folded into c1): u_k = gate input ----
        float c1s = gm * c1;
        float t23 = c2 * c3;
        float u1  = c0 * c1s;
        float u0  = c1s * t23;
        float u2  = u1 * c2;
        float u3  = u1 * t23;

        // ---- gate nonlinearity: v = fma(A, tanh(u), B)  (1 MUFU each) ----
        float v0 = fmaf(gA, tanh_ap(u0), gB);
        float v1 = fmaf(gA, tanh_ap(u1), gB);
        float v2 = fmaf(gA, tanh_ap(u2), gB);
        float v3 = fmaf(gA, tanh_ap(u3), gB);

        // ---- gather all 4 gate vectors into every lane (16 independent shfl) ----
        float tg0[4], tg1[4], tg2[4], tg3[4];
#pragma unroll
        for (int s = 0; s < 4; s++) {
            tg0[s] = __shfl_sync(0xffffffffu, v0, s, 4);
            tg1[s] = __shfl_sync(0xffffffffu, v1, s, 4);
            tg2[s] = __shfl_sync(0xffffffffu, v2, s, 4);
            tg3[s] = __shfl_sync(0xffffffffu, v3, s, 4);
        }
        // tgK[s] = gate-s value for wire K. s: 0=f, 1=i, 2=g, 3=o.

        // ---- combine (replicated); tanh(cx) via MUFU.TANH (1 instr) ----
        float hn[4];
#pragma unroll
        for (int k = 0; k < 4; k++) {
            float F = (k==0)?tg0[0]:(k==1)?tg1[0]:(k==2)?tg2[0]:tg3[0];
            float I = (k==0)?tg0[1]:(k==1)?tg1[1]:(k==2)?tg2[1]:tg3[1];
            float G = (k==0)?tg0[2]:(k==1)?tg1[2]:(k==2)?tg2[2]:tg3[2];
            float O = (k==0)?tg0[3]:(k==1)?tg1[3]:(k==2)?tg2[3]:tg3[3];
            float nc = fmaf(F, cx[k], I * G);
            cx[k] = nc;
            hn[k] = O * tanh_ap(nc);                     // o * tanh(cx)
        }
        h0 = hn[0]; h1 = hn[1]; h2 = hn[2]; h3 = hn[3];

        // ---- fused output epilogue (log2-domain logits, quad softmax) ----
        float l0 = fmaf(h3, wt[0].w, fmaf(h2, wt[0].z, fmaf(h1, wt[0].y, fmaf(h0, wt[0].x, bt[0]))));
        float l1 = fmaf(h3, wt[1].w, fmaf(h2, wt[1].z, fmaf(h1, wt[1].y, fmaf(h0, wt[1].x, bt[1]))));
        float l2 = fmaf(h3, wt[2].w, fmaf(h2, wt[2].z, fmaf(h1, wt[2].y, fmaf(h0, wt[2].x, bt[2]))));
        float l3 = fmaf(h3, wt[3].w, fmaf(h2, wt[3].z, fmaf(h1, wt[3].y, fmaf(h0, wt[3].x, bt[3]))));
        float s4 = (ex2_ap(l0) + ex2_ap(l1)) + (ex2_ap(l2) + ex2_ap(l3));
        s4 += __shfl_xor_sync(0xffffffffu, s4, 1);
        s4 += __shfl_xor_sync(0xffffffffu, s4, 2);
        float lsl = lg2_ap(s4);
        float4 o = make_float4((l0 - lsl) * LN2, (l1 - lsl) * LN2,
                               (l2 - lsl) * LN2, (l3 - lsl) * LN2);
        op[((size_t)t * BB + b) * 4 + g] = o;
    }
}

extern "C" void kernel_launch(void* const* d_in, const int* in_sizes, int n_in,
                              void* d_out, int out_size)
{
    const float* x        = (const float*)d_in[0];
    const float* w_gates  = (const float*)d_in[1];
    const float* b_gates  = (const float*)d_in[2];
    const float* rx_theta = (const float*)d_in[3];
    const float* w_tag    = (const float*)d_in[4];
    const float* b_tag    = (const float*)d_in[5];

    fused_kernel<<<128, 64>>>(x, w_gates, b_gates, rx_theta,
                              w_tag, b_tag, (float*)d_out);
}